// round 4
// baseline (speedup 1.0000x reference)
#include <cuda_runtime.h>

#define BATCH 2048
#define TSEQ  512
#define ISZ   14
#define HID   128
#define G4    512          // 4*HID
#define BT    16           // batch rows per CTA
#define NCTA  (BATCH/BT)   // 128
#define KC    32           // k-chunk for weight streaming
#define NTHR  256
#define HSTR  18           // padded row stride (floats) for transposed h

typedef unsigned long long ull;

// Persistent device scratch
__device__ float g_WT[3][HID*G4];   // [0]=Whh0^T [1]=Wih1^T [2]=Whh1^T, layout [k][n]
__device__ float g_Wih0T[ISZ*G4];   // [k][n]
__device__ float g_b0[G4];
__device__ float g_b1[G4];

struct __align__(16) Smem {
    float ws0[ISZ][G4];     // 28672 resident Wih0^T
    float b0[G4];           // 2048
    float b1[G4];           // 2048
    float hT0[HID][HSTR];   // 9216  transposed h, layer 0: [unit][row]
    float hT1[HID][HSTR];   // 9216  transposed h, layer 1
    float xsT[16][HSTR];    // 1152  transposed x slice: [k][row]
    float wbuf[2][KC][G4];  // 131072 double-buffered weight chunks
};

// ---------------- setup: transpose weights, fuse biases -------------------
__global__ void setup_kernel(const float* __restrict__ Wih0, const float* __restrict__ Whh0,
                             const float* __restrict__ bih0, const float* __restrict__ bhh0,
                             const float* __restrict__ Wih1, const float* __restrict__ Whh1,
                             const float* __restrict__ bih1, const float* __restrict__ bhh1)
{
    int idx = blockIdx.x * blockDim.x + threadIdx.x;
    int stride = gridDim.x * blockDim.x;
    for (int t = idx; t < 3*HID*G4; t += stride) {
        int m = t / (HID*G4);
        int r = t % (HID*G4);
        int k = r / G4, n = r % G4;
        const float* src = (m == 0) ? Whh0 : (m == 1) ? Wih1 : Whh1;
        g_WT[m][r] = src[n*HID + k];
    }
    for (int t = idx; t < ISZ*G4; t += stride) {
        int k = t / G4, n = t % G4;
        g_Wih0T[t] = Wih0[n*ISZ + k];
    }
    for (int n = idx; n < G4; n += stride) {
        g_b0[n] = bih0[n] + bhh0[n];
        g_b1[n] = bih1[n] + bhh1[n];
    }
}

// ---------------- small helpers -------------------------------------------
__device__ __forceinline__ unsigned smem_u32(const void* p) {
    return (unsigned)__cvta_generic_to_shared(p);
}
__device__ __forceinline__ void cp16(unsigned s, const void* g) {
    asm volatile("cp.async.cg.shared.global [%0], [%1], 16;\n" :: "r"(s), "l"(g));
}
__device__ __forceinline__ void cp4(unsigned s, const void* g) {
    asm volatile("cp.async.ca.shared.global [%0], [%1], 4;\n" :: "r"(s), "l"(g));
}
__device__ __forceinline__ void cp_commit() {
    asm volatile("cp.async.commit_group;\n");
}
__device__ __forceinline__ void cp_wait1() {
    asm volatile("cp.async.wait_group 1;\n");
}

__device__ __forceinline__ ull pk2(float v) {          // {v, v}
    ull r; asm("mov.b64 %0, {%1, %1};" : "=l"(r) : "f"(v)); return r;
}
__device__ __forceinline__ void fma2(ull& d, ull a, ull b) {  // d += a*b (f32x2)
    asm("fma.rn.f32x2 %0, %1, %2, %0;" : "+l"(d) : "l"(a), "l"(b));
}
__device__ __forceinline__ float2 up(ull v) {
    float2 r; asm("mov.b64 {%0, %1}, %2;" : "=f"(r.x), "=f"(r.y) : "l"(v)); return r;
}
__device__ __forceinline__ float sigf(float x) {
    return __fdividef(1.0f, 1.0f + __expf(-x));
}
__device__ __forceinline__ float tanhfast(float x) {
    return 1.0f - __fdividef(2.0f, __expf(2.0f*x) + 1.0f);
}

__device__ __forceinline__ void issue_w(Smem& sm, int logical, int buf, int tid) {
    const float* src = &g_WT[logical >> 2][(logical & 3) * KC * G4];
    unsigned d = smem_u32(&sm.wbuf[buf][0][0]) + (unsigned)tid * 16u;
    const char* s = (const char*)src + tid * 16;
    #pragma unroll
    for (int i = 0; i < (KC*G4*4)/(NTHR*16); i++)   // 16 iters
        cp16(d + i*NTHR*16, s + i*NTHR*16);
}

__device__ __forceinline__ void issue_xs(Smem& sm, const float* __restrict__ x,
                                         int b0i, int t, int tid) {
    if (tid < BT*ISZ) {   // 224 threads
        int rb = tid & 15, kk = tid >> 4;
        cp4(smem_u32(&sm.xsT[kk][rb]),
            x + (size_t)(b0i + rb) * TSEQ * ISZ + (size_t)t * ISZ + kk);
    }
}

// ---------------- packed GEMM chunk ---------------------------------------
// acc[g][rp] (f32x2 over row pairs) += ws[kk][g*HID+jg] * hT[kk][r0 + 2rp..]
__device__ __forceinline__ void gemm_chunk(const float (*__restrict__ ws)[G4],
                                           const float (*__restrict__ hT)[HSTR],
                                           int jg, int r0, ull acc[4][4], int nk)
{
    #pragma unroll 4
    for (int kk = 0; kk < nk; kk++) {
        const float* hrow = &hT[kk][r0];
        ull a0 = *(const ull*)(hrow + 0);
        ull a1 = *(const ull*)(hrow + 2);
        ull a2 = *(const ull*)(hrow + 4);
        ull a3 = *(const ull*)(hrow + 6);
        const float* wr = &ws[kk][jg];
        ull w0 = pk2(wr[0*HID]);
        ull w1 = pk2(wr[1*HID]);
        ull w2 = pk2(wr[2*HID]);
        ull w3 = pk2(wr[3*HID]);
        fma2(acc[0][0], w0, a0); fma2(acc[0][1], w0, a1);
        fma2(acc[0][2], w0, a2); fma2(acc[0][3], w0, a3);
        fma2(acc[1][0], w1, a0); fma2(acc[1][1], w1, a1);
        fma2(acc[1][2], w1, a2); fma2(acc[1][3], w1, a3);
        fma2(acc[2][0], w2, a0); fma2(acc[2][1], w2, a1);
        fma2(acc[2][2], w2, a2); fma2(acc[2][3], w2, a3);
        fma2(acc[3][0], w3, a0); fma2(acc[3][1], w3, a1);
        fma2(acc[3][2], w3, a2); fma2(acc[3][3], w3, a3);
    }
}

// ---------------- LSTM elementwise (8 rows of one hidden unit) ------------
__device__ __forceinline__ void lstm_cell(ull acc[4][4], float* cst, float* hdst)
{
    #pragma unroll
    for (int rp = 0; rp < 4; rp++) {
        float2 gi = up(acc[0][rp]);
        float2 gf = up(acc[1][rp]);
        float2 gg = up(acc[2][rp]);
        float2 go = up(acc[3][rp]);
        {
            float c = sigf(gf.x)*cst[2*rp] + sigf(gi.x)*tanhfast(gg.x);
            cst[2*rp] = c;
            hdst[2*rp] = sigf(go.x)*tanhfast(c);
        }
        {
            float c = sigf(gf.y)*cst[2*rp+1] + sigf(gi.y)*tanhfast(gg.y);
            cst[2*rp+1] = c;
            hdst[2*rp+1] = sigf(go.y)*tanhfast(c);
        }
    }
}

// ---------------- fused persistent 2-layer LSTM ---------------------------
__global__ void __launch_bounds__(NTHR, 1)
lstm_fused_kernel(const float* __restrict__ x, const float* __restrict__ Wfc,
                  const float* __restrict__ bfc, float* __restrict__ out)
{
    extern __shared__ float smem_raw[];
    Smem& sm = *reinterpret_cast<Smem*>(smem_raw);
    const int tid = threadIdx.x;
    const int b0i = blockIdx.x * BT;
    const int jg  = tid & 127;        // hidden unit owned by this thread
    const int r0  = (tid >> 7) * 8;   // first of 8 batch rows

    for (int i = tid; i < ISZ*G4; i += NTHR) (&sm.ws0[0][0])[i] = g_Wih0T[i];
    for (int i = tid; i < G4; i += NTHR) { sm.b0[i] = g_b0[i]; sm.b1[i] = g_b1[i]; }
    for (int i = tid; i < HID*HSTR; i += NTHR) { (&sm.hT0[0][0])[i] = 0.f; (&sm.hT1[0][0])[i] = 0.f; }

    float c0s[8], c1s[8];
    #pragma unroll
    for (int i = 0; i < 8; i++) { c0s[i] = 0.f; c1s[i] = 0.f; }

    ull acc[4][4];

    // prime pipeline: chunk 0 of Whh0 (-> buf 0) + x inputs for t=0
    issue_w(sm, 0, 0, tid);
    issue_xs(sm, x, b0i, 0, tid);
    cp_commit();

    for (int t = 0; t < TSEQ; ++t) {
        #pragma unroll 1
        for (int p = 0; p < 12; ++p) {
            if (p < 11) {
                issue_w(sm, p + 1, (p + 1) & 1, tid);
            } else if (t + 1 < TSEQ) {
                issue_w(sm, 0, 0, tid);
                issue_xs(sm, x, b0i, t + 1, tid);
            }
            cp_commit();
            cp_wait1();          // chunk p has landed (this thread)
            __syncthreads();     // visibility of all threads' cp.async data

            if (p == 0) {
                #pragma unroll
                for (int g = 0; g < 4; g++) {
                    ull bv = pk2(sm.b0[g*HID + jg]);
                    acc[g][0] = bv; acc[g][1] = bv; acc[g][2] = bv; acc[g][3] = bv;
                }
                // x projection: K=14 resident in smem
                gemm_chunk(sm.ws0, sm.xsT, jg, r0, acc, ISZ);
            } else if (p == 4) {
                #pragma unroll
                for (int g = 0; g < 4; g++) {
                    ull bv = pk2(sm.b1[g*HID + jg]);
                    acc[g][0] = bv; acc[g][1] = bv; acc[g][2] = bv; acc[g][3] = bv;
                }
            }

            // GEMM chunk p: p 0-3: Whh0*h0(old) | 4-7: Wih1*h0(new) | 8-11: Whh1*h1(old)
            gemm_chunk(sm.wbuf[p & 1],
                       ((p < 8) ? sm.hT0 : sm.hT1) + (p & 3) * KC,
                       jg, r0, acc, KC);

            __syncthreads();     // separate gemm reads from state writes / buffer reuse

            if (p == 3)       lstm_cell(acc, c0s, &sm.hT0[jg][r0]);
            else if (p == 11) lstm_cell(acc, c1s, &sm.hT1[jg][r0]);
        }
    }
    __syncthreads();

    // FC + sigmoid on final h1: out[b] = sigmoid(h1[b] . Wfc + bfc)
    {
        const int w = tid >> 5, l = tid & 31;
        float bias = bfc[0];
        for (int r = w; r < BT; r += NTHR/32) {
            float s = 0.f;
            #pragma unroll
            for (int kk = 0; kk < HID/32; kk++)
                s += sm.hT1[l + kk*32][r] * Wfc[l + kk*32];
            #pragma unroll
            for (int off = 16; off; off >>= 1)
                s += __shfl_xor_sync(0xffffffffu, s, off);
            if (l == 0)
                out[b0i + r] = sigf(s + bias);
        }
    }
}

// ---------------- launch ---------------------------------------------------
extern "C" void kernel_launch(void* const* d_in, const int* in_sizes, int n_in,
                              void* d_out, int out_size)
{
    const float* x    = (const float*)d_in[0];
    const float* Wih0 = (const float*)d_in[1];
    const float* Whh0 = (const float*)d_in[2];
    const float* bih0 = (const float*)d_in[3];
    const float* bhh0 = (const float*)d_in[4];
    const float* Wih1 = (const float*)d_in[5];
    const float* Whh1 = (const float*)d_in[6];
    const float* bih1 = (const float*)d_in[7];
    const float* bhh1 = (const float*)d_in[8];
    const float* Wfc  = (const float*)d_in[9];
    const float* bfc  = (const float*)d_in[10];

    cudaFuncSetAttribute(lstm_fused_kernel,
                         cudaFuncAttributeMaxDynamicSharedMemorySize, (int)sizeof(Smem));

    setup_kernel<<<96, 256>>>(Wih0, Whh0, bih0, bhh0, Wih1, Whh1, bih1, bhh1);
    lstm_fused_kernel<<<NCTA, NTHR, sizeof(Smem)>>>(x, Wfc, bfc, (float*)d_out);
}

// round 8
// speedup vs baseline: 1.7474x; 1.7474x over previous
#include <cuda_runtime.h>
#include <cstdint>

#define TSEQ 512
#define BT   32
#define NCTA 64
#define NTHR 256

// dynamic smem layout (float indices)
#define S_WIH0 0        // 8192 floats: resident Wih0 A-frags
#define S_H0F  8192     // 4096 floats: h0 B-frag tiles [16kt][4nt][32][2]
#define S_H1F  12288    // 4096 floats: h1 B-frag tiles
#define S_XF   16384    // 2 x 512 floats: x B-frag tiles (double buffered)
#define SMEM_FLOATS 17408
#define SMEM_BYTES (SMEM_FLOATS*4)

// persistent device scratch
__device__ float g_WF[3*16*8*4*32*4];              // 786KB frag-major weights (tf32-rounded)
__device__ float g_xF[(size_t)NCTA*TSEQ*512];      // 64MB x B-frags (tf32-rounded)
__device__ float g_b[2][512];                      // fused biases per layer

__device__ __forceinline__ float tf32r(float v){
    uint32_t r; asm("cvt.rna.tf32.f32 %0, %1;" : "=r"(r) : "f"(v));
    return __uint_as_float(r);
}

// ---------------- setup: frag-major packing + tf32 rounding ----------------
__global__ void setup_kernel(const float* __restrict__ x,
    const float* __restrict__ Whh0, const float* __restrict__ Wih1,
    const float* __restrict__ Whh1,
    const float* __restrict__ bih0, const float* __restrict__ bhh0,
    const float* __restrict__ bih1, const float* __restrict__ bhh1)
{
    long long idx0 = blockIdx.x*(long long)blockDim.x + threadIdx.x;
    long long stride = (long long)gridDim.x*blockDim.x;

    // weights: g_WF[m][kt][w][mt][L][i] = W_m[row][col]
    for (long long idx = idx0; idx < 196608; idx += stride){
        int i  = (int)(idx & 3);
        int L  = (int)((idx >> 2) & 31);
        int mt = (int)((idx >> 7) & 3);
        int w  = (int)((idx >> 9) & 7);
        int kt = (int)((idx >> 12) & 15);
        int m  = (int)(idx >> 16);
        int row = mt*128 + 16*w + (L>>2) + (i&1)*8;
        int col = kt*8 + (L&3) + (i>>1)*4;
        const float* W = (m==0) ? Whh0 : (m==1) ? Wih1 : Whh1;
        g_WF[idx] = tf32r(W[row*128 + col]);
    }
    // x B-frags: per (cta,t): e = ((kt*4+nt)*32+L)*2+slot
    for (long long idx = idx0; idx < (long long)NCTA*TSEQ*512; idx += stride){
        int cta = (int)(idx >> 18);
        int rem = (int)(idx & 262143);
        int t   = rem >> 9;
        int e   = rem & 511;
        int slot = e & 1, L = (e>>1)&31, nt = (e>>6)&3, kt = e>>8;
        int b = cta*32 + 8*nt + (L>>2);
        int k = kt*8 + (L&3) + slot*4;
        float v = (k < 14) ? x[((size_t)b*TSEQ + t)*14 + k] : 0.f;
        g_xF[idx] = tf32r(v);
    }
    for (long long n = idx0; n < 512; n += stride){
        g_b[0][n] = bih0[n] + bhh0[n];
        g_b[1][n] = bih1[n] + bhh1[n];
    }
}

// ---------------- device helpers -------------------------------------------
__device__ __forceinline__ void mma8(float* d, uint4 a, uint2 b){
    asm volatile("mma.sync.aligned.m16n8k8.row.col.f32.tf32.tf32.f32 "
        "{%0,%1,%2,%3}, {%4,%5,%6,%7}, {%8,%9}, {%0,%1,%2,%3};"
        : "+f"(d[0]), "+f"(d[1]), "+f"(d[2]), "+f"(d[3])
        : "r"(a.x), "r"(a.y), "r"(a.z), "r"(a.w), "r"(b.x), "r"(b.y));
}
__device__ __forceinline__ uint4 ldgA(int m, int kt, int w, int mt, int L){
    const uint4* p = (const uint4*)g_WF;
    return __ldg(p + ((((m*16 + kt)*8 + w)*4 + mt)*32 + L));
}
__device__ __forceinline__ uint2 ldsB(const float* hF, int kt, int nt, int L){
    return *(const uint2*)(hF + ((kt*4 + nt)*32 + L)*2);
}
__device__ __forceinline__ float sigf(float x){ return __fdividef(1.0f, 1.0f + __expf(-x)); }
__device__ __forceinline__ float tanhfast(float x){ return 1.0f - __fdividef(2.0f, __expf(2.0f*x) + 1.0f); }

__device__ __forceinline__ void cp_x(float* dst, const float* src, int tid){
    unsigned d = (unsigned)__cvta_generic_to_shared(dst + tid*2);
    asm volatile("cp.async.ca.shared.global [%0], [%1], 8;" :: "r"(d), "l"(src + tid*2));
}
__device__ __forceinline__ void cp_commit(){ asm volatile("cp.async.commit_group;"); }
__device__ __forceinline__ void cp_wait0(){ asm volatile("cp.async.wait_group 0;"); }

__device__ __forceinline__ void initacc(float (&acc)[4][4][4], const float* bs){
    #pragma unroll
    for (int g = 0; g < 4; g++)
        #pragma unroll
        for (int nt = 0; nt < 4; nt++){
            acc[g][nt][0] = bs[g*2];   acc[g][nt][1] = bs[g*2];
            acc[g][nt][2] = bs[g*2+1]; acc[g][nt][3] = bs[g*2+1];
        }
}

// streamed GEMM: acc += W_m(warp slice) x hF, K=128, LDG depth-2 pipeline
__device__ __forceinline__ void gemm_stream(int m, float (&acc)[4][4][4],
                                            const float* hF, int w, int L)
{
    uint4 A[3][4];
    uint2 B[2][4];
    #pragma unroll
    for (int mt = 0; mt < 4; mt++){
        A[0][mt] = ldgA(m, 0, w, mt, L);
        A[1][mt] = ldgA(m, 1, w, mt, L);
    }
    #pragma unroll
    for (int nt = 0; nt < 4; nt++) B[0][nt] = ldsB(hF, 0, nt, L);
    #pragma unroll
    for (int kt = 0; kt < 16; kt++){
        if (kt < 14){
            #pragma unroll
            for (int mt = 0; mt < 4; mt++) A[(kt+2)%3][mt] = ldgA(m, kt+2, w, mt, L);
        }
        if (kt < 15){
            #pragma unroll
            for (int nt = 0; nt < 4; nt++) B[(kt+1)&1][nt] = ldsB(hF, kt+1, nt, L);
        }
        #pragma unroll
        for (int mt = 0; mt < 4; mt++)
            #pragma unroll
            for (int nt = 0; nt < 4; nt++)
                mma8(acc[mt][nt], A[kt%3][mt], B[kt&1][nt]);
    }
}

// x projection: A = resident Wih0 frags in smem, B = x frags, K=16
__device__ __forceinline__ void gemm_x(float (&acc)[4][4][4], const float* swih0,
                                       const float* xf, int w, int L)
{
    #pragma unroll
    for (int kt = 0; kt < 2; kt++){
        uint4 a[4]; uint2 b[4];
        #pragma unroll
        for (int mt = 0; mt < 4; mt++)
            a[mt] = *(const uint4*)(swih0 + (((w*2 + kt)*4 + mt)*32 + L)*4);
        #pragma unroll
        for (int nt = 0; nt < 4; nt++)
            b[nt] = *(const uint2*)(xf + ((kt*4 + nt)*32 + L)*2);
        #pragma unroll
        for (int mt = 0; mt < 4; mt++)
            #pragma unroll
            for (int nt = 0; nt < 4; nt++)
                mma8(acc[mt][nt], a[mt], b[nt]);
    }
}

// LSTM cell epilogue: thread-local gates -> c,h; h stored to B-frag smem
__device__ __forceinline__ void epi(float (&acc)[4][4][4], float* cst, float* hF,
                                    int w, int L)
{
    const int c3 = (L>>2)&3, slot = (L>>2)>>2;
    #pragma unroll
    for (int half = 0; half < 2; half++){
        const int kt = 2*w + half;
        #pragma unroll
        for (int nt = 0; nt < 4; nt++)
            #pragma unroll
            for (int j = 0; j < 2; j++){
                int d = half*2 + j;
                float i_ = sigf(acc[0][nt][d]);
                float f_ = sigf(acc[1][nt][d]);
                float g_ = tanhfast(acc[2][nt][d]);
                float o_ = sigf(acc[3][nt][d]);
                int ci = half*8 + nt*2 + j;
                float cc = f_*cst[ci] + i_*g_;
                cst[ci] = cc;
                float h = o_*tanhfast(cc);
                int lane2 = ((2*(L&3) + j) << 2) | c3;
                hF[((kt*4 + nt)*32 + lane2)*2 + slot] = tf32r(h);
            }
    }
}

// ---------------- main persistent kernel ------------------------------------
__global__ void __launch_bounds__(NTHR, 1)
lstm_mma_kernel(const float* __restrict__ Wih0, const float* __restrict__ Wfc,
                const float* __restrict__ bfc, float* __restrict__ out)
{
    extern __shared__ float sm[];
    const int tid = threadIdx.x, w = tid >> 5, L = tid & 31;

    // resident Wih0 A-frags: [w][kt][mt][L][i], K padded 14->16
    for (int idx = tid; idx < 8192; idx += NTHR){
        int i = idx & 3, l = (idx>>2)&31, mt = (idx>>7)&3, kt = (idx>>9)&1, ww = idx>>10;
        int row = mt*128 + 16*ww + (l>>2) + (i&1)*8;
        int col = kt*8 + (l&3) + (i>>1)*4;
        sm[S_WIH0 + idx] = (col < 14) ? tf32r(Wih0[row*14 + col]) : 0.f;
    }
    for (int idx = tid; idx < 8192; idx += NTHR) sm[S_H0F + idx] = 0.f;

    const int u_lo = 16*w + (L>>2), u_hi = u_lo + 8;
    float bs0[8], bs1[8];
    #pragma unroll
    for (int g = 0; g < 4; g++){
        bs0[g*2]   = g_b[0][g*128 + u_lo];
        bs0[g*2+1] = g_b[0][g*128 + u_hi];
        bs1[g*2]   = g_b[1][g*128 + u_lo];
        bs1[g*2+1] = g_b[1][g*128 + u_hi];
    }
    float c0[16], c1[16];
    #pragma unroll
    for (int i = 0; i < 16; i++){ c0[i] = 0.f; c1[i] = 0.f; }

    const float* xsrc = g_xF + (size_t)blockIdx.x*TSEQ*512;
    cp_x(sm + S_XF, xsrc, tid);              // t=0 frags
    cp_commit();
    cp_wait0();
    __syncthreads();

    float acc[4][4][4];

    for (int t = 0; t < TSEQ; t++){
        // ---- layer 0: bias + x-proj + Whh0 * h0_old ----
        initacc(acc, bs0);
        gemm_x(acc, sm + S_WIH0, sm + S_XF + (t&1)*512, w, L);
        gemm_stream(0, acc, sm + S_H0F, w, L);
        __syncthreads();                      // everyone done reading h0F_old
        epi(acc, c0, sm + S_H0F, w, L);
        __syncthreads();                      // h0F_new visible

        // ---- layer 1: bias + Wih1 * h0_new + Whh1 * h1_old ----
        initacc(acc, bs1);
        if (t + 1 < TSEQ){
            cp_x(sm + S_XF + ((t+1)&1)*512, xsrc + (size_t)(t+1)*512, tid);
            cp_commit();
        }
        gemm_stream(1, acc, sm + S_H0F, w, L);
        gemm_stream(2, acc, sm + S_H1F, w, L);
        cp_wait0();
        __syncthreads();                      // everyone done reading h1F_old
        epi(acc, c1, sm + S_H1F, w, L);
        __syncthreads();                      // h1F_new + x visible
    }

    // ---- FC + sigmoid on final h1 ----
    {
        float bias = bfc[0];
        #pragma unroll
        for (int bb = 0; bb < 4; bb++){
            int b = w*4 + bb;
            float s = 0.f;
            #pragma unroll
            for (int q = 0; q < 4; q++){
                int u = L + 32*q;
                int kt = u>>3, cc3 = u&3, sl = (u>>2)&1, nt = b>>3;
                int lane2 = ((b&7)<<2) | cc3;
                s += sm[S_H1F + ((kt*4+nt)*32 + lane2)*2 + sl] * __ldg(Wfc + u);
            }
            #pragma unroll
            for (int off = 16; off; off >>= 1) s += __shfl_xor_sync(0xffffffffu, s, off);
            if (L == 0) out[blockIdx.x*BT + b] = sigf(s + bias);
        }
    }
}

// ---------------- launch ----------------------------------------------------
extern "C" void kernel_launch(void* const* d_in, const int* in_sizes, int n_in,
                              void* d_out, int out_size)
{
    const float* x    = (const float*)d_in[0];
    const float* Wih0 = (const float*)d_in[1];
    const float* Whh0 = (const float*)d_in[2];
    const float* bih0 = (const float*)d_in[3];
    const float* bhh0 = (const float*)d_in[4];
    const float* Wih1 = (const float*)d_in[5];
    const float* Whh1 = (const float*)d_in[6];
    const float* bih1 = (const float*)d_in[7];
    const float* bhh1 = (const float*)d_in[8];
    const float* Wfc  = (const float*)d_in[9];
    const float* bfc  = (const float*)d_in[10];

    cudaFuncSetAttribute(lstm_mma_kernel,
                         cudaFuncAttributeMaxDynamicSharedMemorySize, SMEM_BYTES);

    setup_kernel<<<4096, 256>>>(x, Whh0, Wih1, Whh1, bih0, bhh0, bih1, bhh1);
    lstm_mma_kernel<<<NCTA, NTHR, SMEM_BYTES>>>(Wih0, Wfc, bfc, (float*)d_out);
}

// round 9
// speedup vs baseline: 3.0648x; 1.7539x over previous
#include <cuda_runtime.h>
#include <cstdint>

#define TSEQ 512
#define BT   32
#define NCTA 64
#define NTHR 256

// dynamic smem layout (float indices)
#define S_WIH0 0        // 8192 floats: resident Wih0 A-frags
#define S_H0F  8192     // 4096 floats: h0 B-frag tiles [16kt][4nt][32][2]
#define S_H1F  12288    // 4096 floats: h1 B-frag tiles
#define S_XF   16384    // 2 x 512 floats: x B-frag tiles (double buffered)
#define SMEM_FLOATS 17408
#define SMEM_BYTES (SMEM_FLOATS*4)

// persistent device scratch
__device__ float g_WF[48*8*4*32*4];                // frag-major weights (tf32-rounded), q-major
__device__ float g_xF[(size_t)NCTA*TSEQ*512];      // 64MB x B-frags (tf32-rounded)
__device__ float g_b[2][512];                      // fused biases per layer

__device__ __forceinline__ float tf32r(float v){
    uint32_t r; asm("cvt.rna.tf32.f32 %0, %1;" : "=r"(r) : "f"(v));
    return __uint_as_float(r);
}

// ---------------- setup: frag-major packing + tf32 rounding ----------------
// q = m*16 + kt, m: 0=Whh0 (seg0), 1=Wih1 (seg1), 2=Whh1 (seg2)
__global__ void setup_kernel(const float* __restrict__ x,
    const float* __restrict__ Whh0, const float* __restrict__ Wih1,
    const float* __restrict__ Whh1,
    const float* __restrict__ bih0, const float* __restrict__ bhh0,
    const float* __restrict__ bih1, const float* __restrict__ bhh1)
{
    long long idx0 = blockIdx.x*(long long)blockDim.x + threadIdx.x;
    long long stride = (long long)gridDim.x*blockDim.x;

    // weights: g_WF[q][w][mt][L][i] = W_m[row][col]
    for (long long idx = idx0; idx < 196608; idx += stride){
        int i  = (int)(idx & 3);
        int L  = (int)((idx >> 2) & 31);
        int mt = (int)((idx >> 7) & 3);
        int w  = (int)((idx >> 9) & 7);
        int q  = (int)(idx >> 12);
        int m  = q >> 4, kt = q & 15;
        int row = mt*128 + 16*w + (L>>2) + (i&1)*8;
        int col = kt*8 + (L&3) + (i>>1)*4;
        const float* W = (m==0) ? Whh0 : (m==1) ? Wih1 : Whh1;
        g_WF[idx] = tf32r(W[row*128 + col]);
    }
    // x B-frags: per (cta,t): e = ((kt*4+nt)*32+L)*2+slot
    for (long long idx = idx0; idx < (long long)NCTA*TSEQ*512; idx += stride){
        int cta = (int)(idx >> 18);
        int rem = (int)(idx & 262143);
        int t   = rem >> 9;
        int e   = rem & 511;
        int slot = e & 1, L = (e>>1)&31, nt = (e>>6)&3, kt = e>>8;
        int b = cta*32 + 8*nt + (L>>2);
        int k = kt*8 + (L&3) + slot*4;
        float v = (k < 14) ? x[((size_t)b*TSEQ + t)*14 + k] : 0.f;
        g_xF[idx] = tf32r(v);
    }
    for (long long n = idx0; n < 512; n += stride){
        g_b[0][n] = bih0[n] + bhh0[n];
        g_b[1][n] = bih1[n] + bhh1[n];
    }
}

// ---------------- device helpers -------------------------------------------
__device__ __forceinline__ void mma8(float* d, uint4 a, uint2 b){
    asm volatile("mma.sync.aligned.m16n8k8.row.col.f32.tf32.tf32.f32 "
        "{%0,%1,%2,%3}, {%4,%5,%6,%7}, {%8,%9}, {%0,%1,%2,%3};"
        : "+f"(d[0]), "+f"(d[1]), "+f"(d[2]), "+f"(d[3])
        : "r"(a.x), "r"(a.y), "r"(a.z), "r"(a.w), "r"(b.x), "r"(b.y));
}
__device__ __forceinline__ uint4 ldgA(int q, int w, int mt, int L){
    const uint4* p = (const uint4*)g_WF;
    return __ldg(p + (((q*8 + w)*4 + mt)*32 + L));
}
__device__ __forceinline__ uint2 ldsB(const float* hF, int kt, int nt, int L){
    return *(const uint2*)(hF + ((kt*4 + nt)*32 + L)*2);
}
__device__ __forceinline__ float tanhapx(float x){
    float r; asm("tanh.approx.f32 %0, %1;" : "=f"(r) : "f"(x)); return r;
}
__device__ __forceinline__ float sigapx(float x){
    return fmaf(tanhapx(0.5f*x), 0.5f, 0.5f);
}

__device__ __forceinline__ void cp_x(float* dst, const float* src, int tid){
    unsigned d = (unsigned)__cvta_generic_to_shared(dst + tid*2);
    asm volatile("cp.async.ca.shared.global [%0], [%1], 8;" :: "r"(d), "l"(src + tid*2));
}
__device__ __forceinline__ void cp_commit(){ asm volatile("cp.async.commit_group;"); }
__device__ __forceinline__ void cp_wait0(){ asm volatile("cp.async.wait_group 0;"); }

__device__ __forceinline__ void initacc(float (&acc)[4][4][4], const float* bs){
    #pragma unroll
    for (int g = 0; g < 4; g++)
        #pragma unroll
        for (int nt = 0; nt < 4; nt++){
            acc[g][nt][0] = bs[g*2];   acc[g][nt][1] = bs[g*2];
            acc[g][nt][2] = bs[g*2+1]; acc[g][nt][3] = bs[g*2+1];
        }
}

// one 16-kt GEMM segment out of the flat 48-kt ring; A ring depth 4,
// each consumed slot is immediately refilled with q+4 (mod 48).
template<int SEG>
__device__ __forceinline__ void gemm_seg(float (&acc)[4][4][4], uint4 (&A)[4][4],
                                         const float* __restrict__ hF, int w, int L)
{
    uint2 B[2][4];
    #pragma unroll
    for (int nt = 0; nt < 4; nt++) B[0][nt] = ldsB(hF, 0, nt, L);
    #pragma unroll
    for (int kt = 0; kt < 16; kt++){
        const int q  = SEG*16 + kt;
        const int qn = (q + 4) % 48;
        if (kt < 15){
            #pragma unroll
            for (int nt = 0; nt < 4; nt++) B[(kt+1)&1][nt] = ldsB(hF, kt+1, nt, L);
        }
        #pragma unroll
        for (int mt = 0; mt < 4; mt++)
            #pragma unroll
            for (int nt = 0; nt < 4; nt++)
                mma8(acc[mt][nt], A[q&3][mt], B[kt&1][nt]);
        #pragma unroll
        for (int mt = 0; mt < 4; mt++)
            A[q&3][mt] = ldgA(qn, w, mt, L);
    }
}

// x projection: A = resident Wih0 frags in smem, B = x frags, K=16
__device__ __forceinline__ void gemm_x(float (&acc)[4][4][4], const float* swih0,
                                       const float* xf, int w, int L)
{
    #pragma unroll
    for (int kt = 0; kt < 2; kt++){
        uint4 a[4]; uint2 b[4];
        #pragma unroll
        for (int mt = 0; mt < 4; mt++)
            a[mt] = *(const uint4*)(swih0 + (((w*2 + kt)*4 + mt)*32 + L)*4);
        #pragma unroll
        for (int nt = 0; nt < 4; nt++)
            b[nt] = *(const uint2*)(xf + ((kt*4 + nt)*32 + L)*2);
        #pragma unroll
        for (int mt = 0; mt < 4; mt++)
            #pragma unroll
            for (int nt = 0; nt < 4; nt++)
                mma8(acc[mt][nt], a[mt], b[nt]);
    }
}

// LSTM cell epilogue: thread-local gates -> c,h; h stored to B-frag smem
__device__ __forceinline__ void epi(float (&acc)[4][4][4], float* cst, float* hF,
                                    int w, int L)
{
    const int c3 = (L>>2)&3, slot = (L>>2)>>2;
    #pragma unroll
    for (int half = 0; half < 2; half++){
        const int kt = 2*w + half;
        #pragma unroll
        for (int nt = 0; nt < 4; nt++)
            #pragma unroll
            for (int j = 0; j < 2; j++){
                int d = half*2 + j;
                float i_ = sigapx(acc[0][nt][d]);
                float f_ = sigapx(acc[1][nt][d]);
                float g_ = tanhapx(acc[2][nt][d]);
                float o_ = sigapx(acc[3][nt][d]);
                int ci = half*8 + nt*2 + j;
                float cc = f_*cst[ci] + i_*g_;
                cst[ci] = cc;
                float h = o_*tanhapx(cc);
                int lane2 = ((2*(L&3) + j) << 2) | c3;
                hF[((kt*4 + nt)*32 + lane2)*2 + slot] = tf32r(h);
            }
    }
}

// ---------------- main persistent kernel ------------------------------------
__global__ void __launch_bounds__(NTHR, 1)
lstm_mma_kernel(const float* __restrict__ Wih0, const float* __restrict__ Wfc,
                const float* __restrict__ bfc, float* __restrict__ out)
{
    extern __shared__ float sm[];
    const int tid = threadIdx.x, w = tid >> 5, L = tid & 31;

    // resident Wih0 A-frags: [w][kt][mt][L][i], K padded 14->16
    for (int idx = tid; idx < 8192; idx += NTHR){
        int i = idx & 3, l = (idx>>2)&31, mt = (idx>>7)&3, kt = (idx>>9)&1, ww = idx>>10;
        int row = mt*128 + 16*ww + (l>>2) + (i&1)*8;
        int col = kt*8 + (l&3) + (i>>1)*4;
        sm[S_WIH0 + idx] = (col < 14) ? tf32r(Wih0[row*14 + col]) : 0.f;
    }
    for (int idx = tid; idx < 8192; idx += NTHR) sm[S_H0F + idx] = 0.f;

    const int u_lo = 16*w + (L>>2), u_hi = u_lo + 8;
    float bs0[8], bs1[8];
    #pragma unroll
    for (int g = 0; g < 4; g++){
        bs0[g*2]   = g_b[0][g*128 + u_lo];
        bs0[g*2+1] = g_b[0][g*128 + u_hi];
        bs1[g*2]   = g_b[1][g*128 + u_lo];
        bs1[g*2+1] = g_b[1][g*128 + u_hi];
    }
    float c0[16], c1[16];
    #pragma unroll
    for (int i = 0; i < 16; i++){ c0[i] = 0.f; c1[i] = 0.f; }

    const float* xsrc = g_xF + (size_t)blockIdx.x*TSEQ*512;
    cp_x(sm + S_XF, xsrc, tid);              // t=0 frags
    cp_commit();
    cp_wait0();
    __syncthreads();

    float acc[4][4][4];
    uint4 A[4][4];
    #pragma unroll
    for (int q = 0; q < 4; q++)
        #pragma unroll
        for (int mt = 0; mt < 4; mt++)
            A[q][mt] = ldgA(q, w, mt, L);

    for (int t = 0; t < TSEQ; t++){
        // ---- layer 0: bias + x-proj + Whh0 * h0_old ----
        initacc(acc, bs0);
        gemm_x(acc, sm + S_WIH0, sm + S_XF + (t&1)*512, w, L);
        gemm_seg<0>(acc, A, sm + S_H0F, w, L);
        __syncthreads();                      // everyone done reading h0F_old
        epi(acc, c0, sm + S_H0F, w, L);
        __syncthreads();                      // h0F_new visible

        // ---- layer 1: bias + Wih1 * h0_new + Whh1 * h1_old ----
        initacc(acc, bs1);
        if (t + 1 < TSEQ){
            cp_x(sm + S_XF + ((t+1)&1)*512, xsrc + (size_t)(t+1)*512, tid);
            cp_commit();
        }
        gemm_seg<1>(acc, A, sm + S_H0F, w, L);
        gemm_seg<2>(acc, A, sm + S_H1F, w, L);
        cp_wait0();
        __syncthreads();                      // everyone done reading h1F_old
        epi(acc, c1, sm + S_H1F, w, L);
        __syncthreads();                      // h1F_new + x visible
    }

    // ---- FC + sigmoid on final h1 ----
    {
        float bias = bfc[0];
        #pragma unroll
        for (int bb = 0; bb < 4; bb++){
            int b = w*4 + bb;
            float s = 0.f;
            #pragma unroll
            for (int q = 0; q < 4; q++){
                int u = L + 32*q;
                int kt = u>>3, cc3 = u&3, sl = (u>>2)&1, nt = b>>3;
                int lane2 = ((b&7)<<2) | cc3;
                s += sm[S_H1F + ((kt*4+nt)*32 + lane2)*2 + sl] * __ldg(Wfc + u);
            }
            #pragma unroll
            for (int off = 16; off; off >>= 1) s += __shfl_xor_sync(0xffffffffu, s, off);
            if (L == 0) out[blockIdx.x*BT + b] = sigapx(s + bias);
        }
    }
}

// ---------------- launch ----------------------------------------------------
extern "C" void kernel_launch(void* const* d_in, const int* in_sizes, int n_in,
                              void* d_out, int out_size)
{
    const float* x    = (const float*)d_in[0];
    const float* Wih0 = (const float*)d_in[1];
    const float* Whh0 = (const float*)d_in[2];
    const float* bih0 = (const float*)d_in[3];
    const float* bhh0 = (const float*)d_in[4];
    const float* Wih1 = (const float*)d_in[5];
    const float* Whh1 = (const float*)d_in[6];
    const float* bih1 = (const float*)d_in[7];
    const float* bhh1 = (const float*)d_in[8];
    const float* Wfc  = (const float*)d_in[9];
    const float* bfc  = (const float*)d_in[10];

    cudaFuncSetAttribute(lstm_mma_kernel,
                         cudaFuncAttributeMaxDynamicSharedMemorySize, SMEM_BYTES);

    setup_kernel<<<4096, 256>>>(x, Whh0, Wih1, Whh1, bih0, bhh0, bih1, bhh1);
    lstm_mma_kernel<<<NCTA, NTHR, SMEM_BYTES>>>(Wih0, Wfc, bfc, (float*)d_out);
}

// round 10
// speedup vs baseline: 4.8773x; 1.5914x over previous
#include <cuda_runtime.h>
#include <cstdint>

#define TSEQ 512
#define BT   32
#define NCTA 64
#define NTHR 256

// dynamic smem layout (u32 word indices)
#define S_WIH0 0      // 4096 words: resident Wih0 bf16 A-frags [w][mt][L][4]
#define S_H0F  4096   // 2048 words: h0 bf16 B-frags [8kt][4nt][32L][2]
#define S_H1F  6144   // 2048 words: h1 bf16 B-frags
#define S_XF   8192   // 2 x 256 words: x bf16 B-frags (double buffered)
#define SMEM_WORDS 8704
#define SMEM_BYTES (SMEM_WORDS*4)

// persistent device scratch
__device__ uint32_t g_WF[24*8*4*32*4];            // 393KB bf16 frag-major weights, q-major
__device__ uint32_t g_xB[(size_t)NCTA*TSEQ*256];  // 32MB bf16 x B-frags
__device__ float g_b[2][512];                     // fused biases

__device__ __forceinline__ uint32_t bf2(float a, float b){
    uint32_t r;
    asm("{.reg .b16 lo, hi;\n\tcvt.rn.bf16.f32 lo, %1;\n\tcvt.rn.bf16.f32 hi, %2;\n\t"
        "mov.b32 %0, {lo, hi};}" : "=r"(r) : "f"(a), "f"(b));
    return r;
}
__device__ __forceinline__ uint16_t bfr(float v){
    uint16_t r; asm("cvt.rn.bf16.f32 %0, %1;" : "=h"(r) : "f"(v)); return r;
}

// ---------------- setup: bf16 frag-major packing ---------------------------
// q = m*8 + kt; m: 0=Whh0(seg0), 1=Wih1(seg1), 2=Whh1(seg2)
__global__ void setup_kernel(const float* __restrict__ x,
    const float* __restrict__ Whh0, const float* __restrict__ Wih1,
    const float* __restrict__ Whh1,
    const float* __restrict__ bih0, const float* __restrict__ bhh0,
    const float* __restrict__ bih1, const float* __restrict__ bhh1)
{
    long long idx0 = blockIdx.x*(long long)blockDim.x + threadIdx.x;
    long long stride = (long long)gridDim.x*blockDim.x;

    // weights: g_WF[q][w][mt][L][i] (u32 = bf16x2)
    for (long long idx = idx0; idx < 98304; idx += stride){
        int i  = (int)(idx & 3);
        int L  = (int)((idx >> 2) & 31);
        int mt = (int)((idx >> 7) & 3);
        int w  = (int)((idx >> 9) & 7);
        int q  = (int)(idx >> 12);
        int m  = q >> 3, kt = q & 7;
        int gid = L >> 2, tig = L & 3;
        int row = mt*128 + 16*w + gid + (i&1)*8;
        int col = kt*16 + 2*tig + (i>>1)*8;
        const float* W = (m==0) ? Whh0 : (m==1) ? Wih1 : Whh1;
        g_WF[idx] = bf2(W[row*128 + col], W[row*128 + col + 1]);
    }
    // x B-frags: per (cta,t) 256 words, e = (nt*32+L)*2+reg
    for (long long idx = idx0; idx < (long long)NCTA*TSEQ*256; idx += stride){
        int cta = (int)(idx >> 17);
        int rem = (int)(idx & 131071);
        int t   = rem >> 8;
        int e   = rem & 255;
        int reg = e & 1, L = (e>>1)&31, nt = e>>6;
        int gid = L>>2, tig = L&3;
        int b = cta*32 + nt*8 + gid;
        int k0 = 2*tig + reg*8;
        float v0 = (k0   < 14) ? x[((size_t)b*TSEQ + t)*14 + k0    ] : 0.f;
        float v1 = (k0+1 < 14) ? x[((size_t)b*TSEQ + t)*14 + k0 + 1] : 0.f;
        g_xB[idx] = bf2(v0, v1);
    }
    for (long long n = idx0; n < 512; n += stride){
        g_b[0][n] = bih0[n] + bhh0[n];
        g_b[1][n] = bih1[n] + bhh1[n];
    }
}

// ---------------- device helpers -------------------------------------------
__device__ __forceinline__ void mma16(float* d, uint4 a, uint2 b){
    asm volatile("mma.sync.aligned.m16n8k16.row.col.f32.bf16.bf16.f32 "
        "{%0,%1,%2,%3}, {%4,%5,%6,%7}, {%8,%9}, {%0,%1,%2,%3};"
        : "+f"(d[0]), "+f"(d[1]), "+f"(d[2]), "+f"(d[3])
        : "r"(a.x), "r"(a.y), "r"(a.z), "r"(a.w), "r"(b.x), "r"(b.y));
}
__device__ __forceinline__ uint4 ldgA(int q, int w, int mt, int L){
    const uint4* p = (const uint4*)g_WF;
    return __ldg(p + (((q*8 + w)*4 + mt)*32 + L));
}
__device__ __forceinline__ float tanhapx(float x){
    float r; asm("tanh.approx.f32 %0, %1;" : "=f"(r) : "f"(x)); return r;
}
__device__ __forceinline__ float sigapx(float x){
    return fmaf(tanhapx(0.5f*x), 0.5f, 0.5f);
}
__device__ __forceinline__ void cp_x(uint32_t* dst, const uint32_t* src, int tid){
    unsigned d = (unsigned)__cvta_generic_to_shared(dst + tid);
    asm volatile("cp.async.ca.shared.global [%0], [%1], 4;" :: "r"(d), "l"(src + tid));
}
__device__ __forceinline__ void cp_commit(){ asm volatile("cp.async.commit_group;"); }
__device__ __forceinline__ void cp_wait0(){ asm volatile("cp.async.wait_group 0;"); }

__device__ __forceinline__ void initacc(float (&acc)[4][4][4], const float* bs){
    #pragma unroll
    for (int g = 0; g < 4; g++)
        #pragma unroll
        for (int nt = 0; nt < 4; nt++){
            acc[g][nt][0] = bs[g*2];   acc[g][nt][1] = bs[g*2];
            acc[g][nt][2] = bs[g*2+1]; acc[g][nt][3] = bs[g*2+1];
        }
}

// one 8-kt GEMM segment of the flat 24-q ring; A ring depth 4, refill q+4 mod 24
template<int SEG>
__device__ __forceinline__ void gemm_seg(float (&acc)[4][4][4], uint4 (&A)[4][4],
                                         const uint32_t* __restrict__ hF, int w, int L)
{
    uint2 B[2][4];
    #pragma unroll
    for (int nt = 0; nt < 4; nt++) B[0][nt] = *(const uint2*)(hF + (nt*32 + L)*2);
    #pragma unroll
    for (int kt = 0; kt < 8; kt++){
        const int q  = SEG*8 + kt;
        const int qn = (q + 4) % 24;
        if (kt < 7){
            #pragma unroll
            for (int nt = 0; nt < 4; nt++)
                B[(kt+1)&1][nt] = *(const uint2*)(hF + (((kt+1)*4 + nt)*32 + L)*2);
        }
        #pragma unroll
        for (int mt = 0; mt < 4; mt++)
            #pragma unroll
            for (int nt = 0; nt < 4; nt++)
                mma16(acc[mt][nt], A[q&3][mt], B[kt&1][nt]);
        #pragma unroll
        for (int mt = 0; mt < 4; mt++)
            A[q&3][mt] = ldgA(qn, w, mt, L);
    }
}

// x projection: A = resident Wih0 frags (smem), B = x frags, single K=16 tile
__device__ __forceinline__ void gemm_x(float (&acc)[4][4][4], const uint32_t* smW,
                                       const uint32_t* xf, int w, int L)
{
    uint4 a[4]; uint2 b[4];
    #pragma unroll
    for (int mt = 0; mt < 4; mt++)
        a[mt] = *(const uint4*)(smW + ((w*4 + mt)*32 + L)*4);
    #pragma unroll
    for (int nt = 0; nt < 4; nt++)
        b[nt] = *(const uint2*)(xf + (nt*32 + L)*2);
    #pragma unroll
    for (int mt = 0; mt < 4; mt++)
        #pragma unroll
        for (int nt = 0; nt < 4; nt++)
            mma16(acc[mt][nt], a[mt], b[nt]);
}

// LSTM cell epilogue: gates -> c,h; h scattered as bf16 into B-frag smem
__device__ __forceinline__ void epi(float (&acc)[4][4][4], float* cst,
                                    uint32_t* hF, int w, int L)
{
    uint16_t* hs = (uint16_t*)hF;
    const int gid = L >> 2, tig = L & 3;
    #pragma unroll
    for (int hh = 0; hh < 2; hh++)
        #pragma unroll
        for (int nt = 0; nt < 4; nt++)
            #pragma unroll
            for (int j = 0; j < 2; j++){
                int d = hh*2 + j;
                float i_ = sigapx(acc[0][nt][d]);
                float f_ = sigapx(acc[1][nt][d]);
                float g_ = tanhapx(acc[2][nt][d]);
                float o_ = sigapx(acc[3][nt][d]);
                int ci = hh*8 + nt*2 + j;
                float cc = f_*cst[ci] + i_*g_;
                cst[ci] = cc;
                float h = o_*tanhapx(cc);
                // u = 16w + gid + 8hh ; b = nt*8 + 2tig + j
                int Lp = (2*tig + j)*4 + (gid >> 1);
                int off16 = ((w*4 + nt)*32 + Lp)*4 + hh*2 + (gid & 1);
                hs[off16] = bfr(h);
            }
}

// ---------------- main persistent kernel ------------------------------------
__global__ void __launch_bounds__(NTHR, 1)
lstm_mma_kernel(const float* __restrict__ Wih0, const float* __restrict__ Wfc,
                const float* __restrict__ bfc, float* __restrict__ out)
{
    extern __shared__ uint32_t sm[];
    const int tid = threadIdx.x, w = tid >> 5, L = tid & 31;

    // resident Wih0 bf16 A-frags [w][mt][L][4], K padded 14->16
    for (int idx = tid; idx < 4096; idx += NTHR){
        int i = idx & 3, l = (idx>>2)&31, mt = (idx>>7)&3, ww = idx>>9;
        int gid = l>>2, tig = l&3;
        int row = mt*128 + 16*ww + gid + (i&1)*8;
        int c0 = 2*tig + (i>>1)*8;
        float v0 = (c0   < 14) ? Wih0[row*14 + c0    ] : 0.f;
        float v1 = (c0+1 < 14) ? Wih0[row*14 + c0 + 1] : 0.f;
        sm[S_WIH0 + idx] = bf2(v0, v1);
    }
    for (int idx = tid; idx < 4096; idx += NTHR) sm[S_H0F + idx] = 0u;

    const int u_lo = 16*w + (L>>2), u_hi = u_lo + 8;
    float bs0[8], bs1[8];
    #pragma unroll
    for (int g = 0; g < 4; g++){
        bs0[g*2]   = g_b[0][g*128 + u_lo];
        bs0[g*2+1] = g_b[0][g*128 + u_hi];
        bs1[g*2]   = g_b[1][g*128 + u_lo];
        bs1[g*2+1] = g_b[1][g*128 + u_hi];
    }
    float c0[16], c1[16];
    #pragma unroll
    for (int i = 0; i < 16; i++){ c0[i] = 0.f; c1[i] = 0.f; }

    const uint32_t* xsrc = g_xB + (size_t)blockIdx.x*TSEQ*256;
    cp_x(sm + S_XF, xsrc, tid);
    cp_commit();
    cp_wait0();
    __syncthreads();

    float acc[4][4][4];
    uint4 A[4][4];
    #pragma unroll
    for (int q = 0; q < 4; q++)
        #pragma unroll
        for (int mt = 0; mt < 4; mt++)
            A[q][mt] = ldgA(q, w, mt, L);

    for (int t = 0; t < TSEQ; t++){
        // ---- layer 0: bias + x-proj + Whh0 * h0_old ----
        initacc(acc, bs0);
        gemm_x(acc, sm + S_WIH0, sm + S_XF + (t&1)*256, w, L);
        gemm_seg<0>(acc, A, sm + S_H0F, w, L);
        __syncthreads();                      // all reads of h0F_old done
        epi(acc, c0, sm + S_H0F, w, L);
        __syncthreads();                      // h0F_new visible

        // ---- layer 1: bias + Wih1 * h0_new + Whh1 * h1_old ----
        initacc(acc, bs1);
        if (t + 1 < TSEQ){
            cp_x(sm + S_XF + ((t+1)&1)*256, xsrc + (size_t)(t+1)*256, tid);
            cp_commit();
        }
        gemm_seg<1>(acc, A, sm + S_H0F, w, L);
        gemm_seg<2>(acc, A, sm + S_H1F, w, L);
        cp_wait0();
        __syncthreads();                      // all reads of h1F_old done
        epi(acc, c1, sm + S_H1F, w, L);
        __syncthreads();                      // h1F_new + x visible
    }

    // ---- FC + sigmoid on final h1 ----
    {
        const uint16_t* hs = (const uint16_t*)(sm + S_H1F);
        float bias = bfc[0];
        #pragma unroll
        for (int bb = 0; bb < 4; bb++){
            int b = w*4 + bb;
            float s = 0.f;
            #pragma unroll
            for (int qq = 0; qq < 4; qq++){
                int u = L + 32*qq;
                int kt = u >> 4, k = u & 15;
                int reg = k >> 3, kk = k & 7;
                int Lp = (b & 7)*4 + (kk >> 1);
                int off16 = ((kt*4 + (b>>3))*32 + Lp)*4 + reg*2 + (kk & 1);
                float hv = __uint_as_float(((uint32_t)hs[off16]) << 16);
                s += hv * __ldg(Wfc + u);
            }
            #pragma unroll
            for (int off = 16; off; off >>= 1) s += __shfl_xor_sync(0xffffffffu, s, off);
            if (L == 0) out[blockIdx.x*BT + b] = sigapx(s + bias);
        }
    }
}

// ---------------- launch ----------------------------------------------------
extern "C" void kernel_launch(void* const* d_in, const int* in_sizes, int n_in,
                              void* d_out, int out_size)
{
    const float* x    = (const float*)d_in[0];
    const float* Wih0 = (const float*)d_in[1];
    const float* Whh0 = (const float*)d_in[2];
    const float* bih0 = (const float*)d_in[3];
    const float* bhh0 = (const float*)d_in[4];
    const float* Wih1 = (const float*)d_in[5];
    const float* Whh1 = (const float*)d_in[6];
    const float* bih1 = (const float*)d_in[7];
    const float* bhh1 = (const float*)d_in[8];
    const float* Wfc  = (const float*)d_in[9];
    const float* bfc  = (const float*)d_in[10];

    cudaFuncSetAttribute(lstm_mma_kernel,
                         cudaFuncAttributeMaxDynamicSharedMemorySize, SMEM_BYTES);

    setup_kernel<<<4096, 256>>>(x, Whh0, Wih1, Whh1, bih0, bhh0, bih1, bhh1);
    lstm_mma_kernel<<<NCTA, NTHR, SMEM_BYTES>>>(Wih0, Wfc, bfc, (float*)d_out);
}